// round 2
// baseline (speedup 1.0000x reference)
#include <cuda_runtime.h>
#include <cstdint>

#define NMAX   50000
#define EMAX   500000
#define ZDIM   136      // 16 (he) x 8 (x) + 8 (x bias lanes)
#define GRAPHS 64
#define EPS    1e-5f

// ---------------- scratch (device globals; no allocation allowed) ----------------
__device__ int      g_cnt[NMAX];                    // degree / histogram
__device__ int      g_off[NMAX + 1];                // CSR offsets
__device__ int      g_cur[NMAX];                    // scatter cursors
__device__ int      g_ssrc[EMAX];                   // dst-sorted src ids
__device__ float4   g_sea[(size_t)EMAX * 2];        // dst-sorted edge_attr (8 floats)
__device__ float    g_pre[(size_t)NMAX * 64];       // NNConv pre-BN output
__device__ float    g_colsum[64];
__device__ float    g_colsq[64];
__device__ int      g_start[GRAPHS + 1];            // graph boundaries in node order
__device__ float    g_gfeat[GRAPHS * 128];
__device__ float    g_y1[GRAPHS * 256];
__device__ float    g_y2[GRAPHS * 128];
__device__ float    g_y3[GRAPHS * 64];

// ---------------- zero small scratch ----------------
__global__ void k_zero(int n) {
    int i = blockIdx.x * blockDim.x + threadIdx.x;
    int stride = gridDim.x * blockDim.x;
    for (int j = i; j < n; j += stride) g_cnt[j] = 0;
    if (i < 64) { g_colsum[i] = 0.f; g_colsq[i] = 0.f; }
}

// ---------------- histogram of dst ----------------
__global__ void k_hist(const int* __restrict__ ei, int E) {
    int e = blockIdx.x * blockDim.x + threadIdx.x;
    if (e < E) atomicAdd(&g_cnt[__ldg(&ei[E + e])], 1);
}

// ---------------- single-block exclusive scan of degrees ----------------
__global__ void k_scan(int N, int E) {
    __shared__ int part[1024];
    int t = threadIdx.x;
    int chunk = (N + 1023) / 1024;
    int beg = t * chunk, end = min(beg + chunk, N);
    int s = 0;
    for (int i = beg; i < end; i++) s += g_cnt[i];
    part[t] = s;
    __syncthreads();
    // Hillis-Steele inclusive scan
    for (int off = 1; off < 1024; off <<= 1) {
        int v = (t >= off) ? part[t - off] : 0;
        __syncthreads();
        part[t] += v;
        __syncthreads();
    }
    int run = (t == 0) ? 0 : part[t - 1];
    for (int i = beg; i < end; i++) {
        int c = g_cnt[i];
        g_off[i] = run;
        g_cur[i] = run;
        run += c;
    }
    if (end == N && beg <= N) g_off[N] = E;
}

// ---------------- graph boundaries (batch is sorted) ----------------
__global__ void k_starts(const int* __restrict__ batch, int N) {
    int g = threadIdx.x;
    if (g >= GRAPHS) return;
    int lo = 0, hi = N;
    while (lo < hi) {
        int mid = (lo + hi) >> 1;
        if (__ldg(&batch[mid]) < g) lo = mid + 1; else hi = mid;
    }
    g_start[g] = lo;
    if (g == 0) g_start[GRAPHS] = N;
}

// ---------------- scatter edge payload into dst-sorted order ----------------
__global__ void k_scatter(const int* __restrict__ ei,
                          const float* __restrict__ ea,
                          int E) {
    int e = blockIdx.x * blockDim.x + threadIdx.x;
    if (e >= E) return;
    int dst = __ldg(&ei[E + e]);
    int src = __ldg(&ei[e]);
    float4 a0 = __ldg((const float4*)(ea + (size_t)e * 8));
    float4 a1 = __ldg((const float4*)(ea + (size_t)e * 8 + 4));
    int pos = atomicAdd(&g_cur[dst], 1);
    g_ssrc[pos] = src;
    g_sea[(size_t)pos * 2]     = a0;
    g_sea[(size_t)pos * 2 + 1] = a1;
}

// ---------------- fused: z-accumulate (atomic-free) + node GEMM + BN stats ----------------
// block = 256 threads, 32 nodes per block.
// Phase 1: 8 threads per node; thread owns j-pair {2*sub, 2*sub+1} of he.
// Phase 2: warp per 4 nodes, lane owns 2 output cols (as old k_node) reading z from shared.
__global__ void k_fused(const float* __restrict__ x,
                        const float* __restrict__ w_e1,
                        const float* __restrict__ b_e1,
                        const float* __restrict__ w_e2,
                        const float* __restrict__ b_e2,
                        const float* __restrict__ root,
                        const float* __restrict__ cbias,
                        int N) {
    extern __shared__ char dynsmem[];
    float2* sWc = (float2*)dynsmem;                      // [136][32] float2 = 34816 B
    float*  sZ  = (float*)(dynsmem + ZDIM * 32 * 8);     // [32][136] float = 17408 B

    __shared__ float  sW1[128];
    __shared__ float  sB1[16];
    __shared__ float2 sRoot[8][32];
    __shared__ float  sCB[64];
    __shared__ float  sInvDeg[32];
    __shared__ float2 redS[8][32];
    __shared__ float2 redQ[8][32];

    int tid = threadIdx.x;

    // ---- load weights ----
    if (tid < 128) sW1[tid] = w_e1[tid];
    if (tid < 16)  sB1[tid] = b_e1[tid];
    for (int idx = tid; idx < ZDIM * 32; idx += blockDim.x) {
        int k = idx >> 5, l = idx & 31;
        int h0 = 2 * l;
        float a, b;
        if (k < 128) {
            int j = k >> 3, f = k & 7;
            a = w_e2[j * 512 + f * 64 + h0];
            b = w_e2[j * 512 + f * 64 + h0 + 1];
        } else {
            int f = k - 128;
            a = b_e2[f * 64 + h0];
            b = b_e2[f * 64 + h0 + 1];
        }
        sWc[k * 32 + l] = make_float2(a, b);
    }
    for (int idx = tid; idx < 8 * 32; idx += blockDim.x) {
        int f = idx >> 5, l = idx & 31;
        sRoot[f][l] = make_float2(root[f * 64 + 2 * l], root[f * 64 + 2 * l + 1]);
    }
    if (tid < 64) sCB[tid] = cbias[tid];
    __syncthreads();

    // ---- phase 1: per-node z accumulation from CSR edges ----
    {
        int gnode = tid >> 3;          // 0..31 node within block
        int sub   = tid & 7;           // owns he[2*sub], he[2*sub+1]
        int n = blockIdx.x * 32 + gnode;
        int j0 = 2 * sub;

        float zacc[16];
        #pragma unroll
        for (int i = 0; i < 16; i++) zacc[i] = 0.f;
        float xs[8];
        #pragma unroll
        for (int i = 0; i < 8; i++) xs[i] = 0.f;

        int deg = 0;
        if (n < N) {
            int o0 = __ldg(&g_off[n]);
            int o1 = __ldg(&g_off[n + 1]);
            deg = o1 - o0;
            for (int i = o0; i < o1; i++) {
                float4 a0 = __ldg(&g_sea[(size_t)i * 2]);
                float4 a1 = __ldg(&g_sea[(size_t)i * 2 + 1]);
                int src = __ldg(&g_ssrc[i]);
                float4 x0 = __ldg((const float4*)(x + (size_t)src * 8));
                float4 x1 = __ldg((const float4*)(x + (size_t)src * 8 + 4));

                float h0 = sB1[j0];
                float h1 = sB1[j0 + 1];
                h0 = fmaf(a0.x, sW1[0 * 16 + j0], h0); h1 = fmaf(a0.x, sW1[0 * 16 + j0 + 1], h1);
                h0 = fmaf(a0.y, sW1[1 * 16 + j0], h0); h1 = fmaf(a0.y, sW1[1 * 16 + j0 + 1], h1);
                h0 = fmaf(a0.z, sW1[2 * 16 + j0], h0); h1 = fmaf(a0.z, sW1[2 * 16 + j0 + 1], h1);
                h0 = fmaf(a0.w, sW1[3 * 16 + j0], h0); h1 = fmaf(a0.w, sW1[3 * 16 + j0 + 1], h1);
                h0 = fmaf(a1.x, sW1[4 * 16 + j0], h0); h1 = fmaf(a1.x, sW1[4 * 16 + j0 + 1], h1);
                h0 = fmaf(a1.y, sW1[5 * 16 + j0], h0); h1 = fmaf(a1.y, sW1[5 * 16 + j0 + 1], h1);
                h0 = fmaf(a1.z, sW1[6 * 16 + j0], h0); h1 = fmaf(a1.z, sW1[6 * 16 + j0 + 1], h1);
                h0 = fmaf(a1.w, sW1[7 * 16 + j0], h0); h1 = fmaf(a1.w, sW1[7 * 16 + j0 + 1], h1);
                h0 = fmaxf(h0, 0.f);
                h1 = fmaxf(h1, 0.f);

                zacc[0] = fmaf(h0, x0.x, zacc[0]);
                zacc[1] = fmaf(h0, x0.y, zacc[1]);
                zacc[2] = fmaf(h0, x0.z, zacc[2]);
                zacc[3] = fmaf(h0, x0.w, zacc[3]);
                zacc[4] = fmaf(h0, x1.x, zacc[4]);
                zacc[5] = fmaf(h0, x1.y, zacc[5]);
                zacc[6] = fmaf(h0, x1.z, zacc[6]);
                zacc[7] = fmaf(h0, x1.w, zacc[7]);
                zacc[8]  = fmaf(h1, x0.x, zacc[8]);
                zacc[9]  = fmaf(h1, x0.y, zacc[9]);
                zacc[10] = fmaf(h1, x0.z, zacc[10]);
                zacc[11] = fmaf(h1, x0.w, zacc[11]);
                zacc[12] = fmaf(h1, x1.x, zacc[12]);
                zacc[13] = fmaf(h1, x1.y, zacc[13]);
                zacc[14] = fmaf(h1, x1.z, zacc[14]);
                zacc[15] = fmaf(h1, x1.w, zacc[15]);

                if (sub == 0) {
                    xs[0] += x0.x; xs[1] += x0.y; xs[2] += x0.z; xs[3] += x0.w;
                    xs[4] += x1.x; xs[5] += x1.y; xs[6] += x1.z; xs[7] += x1.w;
                }
            }
        }
        float* zrow = sZ + gnode * ZDIM;
        #pragma unroll
        for (int f = 0; f < 8; f++) {
            zrow[j0 * 8 + f]       = zacc[f];
            zrow[(j0 + 1) * 8 + f] = zacc[8 + f];
        }
        if (sub == 0) {
            #pragma unroll
            for (int f = 0; f < 8; f++) zrow[128 + f] = xs[f];
            sInvDeg[gnode] = 1.f / fmaxf((float)deg, 1.f);
        }
    }
    __syncthreads();

    // ---- phase 2: pre = (z @ Wc)*invdeg + x@root + bias; BN partial stats ----
    int warp = tid >> 5, lane = tid & 31;
    int nlocbase = warp * 4;
    int nbase = blockIdx.x * 32 + nlocbase;

    int  nn[4];
    bool valid[4];
    #pragma unroll
    for (int i = 0; i < 4; i++) {
        int n = nbase + i;
        valid[i] = (n < N);
        nn[i] = valid[i] ? n : 0;
    }

    const float4* zr0 = (const float4*)(sZ + (nlocbase + 0) * ZDIM);
    const float4* zr1 = (const float4*)(sZ + (nlocbase + 1) * ZDIM);
    const float4* zr2 = (const float4*)(sZ + (nlocbase + 2) * ZDIM);
    const float4* zr3 = (const float4*)(sZ + (nlocbase + 3) * ZDIM);

    float2 agg[4];
    #pragma unroll
    for (int i = 0; i < 4; i++) agg[i] = make_float2(0.f, 0.f);

    #pragma unroll 2
    for (int kk = 0; kk < ZDIM / 4; kk++) {
        float4 z0 = zr0[kk];
        float4 z1 = zr1[kk];
        float4 z2 = zr2[kk];
        float4 z3 = zr3[kk];
        float2 wa = sWc[(4 * kk + 0) * 32 + lane];
        float2 wb = sWc[(4 * kk + 1) * 32 + lane];
        float2 wc = sWc[(4 * kk + 2) * 32 + lane];
        float2 wd = sWc[(4 * kk + 3) * 32 + lane];
        agg[0].x = fmaf(z0.x, wa.x, agg[0].x); agg[0].y = fmaf(z0.x, wa.y, agg[0].y);
        agg[0].x = fmaf(z0.y, wb.x, agg[0].x); agg[0].y = fmaf(z0.y, wb.y, agg[0].y);
        agg[0].x = fmaf(z0.z, wc.x, agg[0].x); agg[0].y = fmaf(z0.z, wc.y, agg[0].y);
        agg[0].x = fmaf(z0.w, wd.x, agg[0].x); agg[0].y = fmaf(z0.w, wd.y, agg[0].y);
        agg[1].x = fmaf(z1.x, wa.x, agg[1].x); agg[1].y = fmaf(z1.x, wa.y, agg[1].y);
        agg[1].x = fmaf(z1.y, wb.x, agg[1].x); agg[1].y = fmaf(z1.y, wb.y, agg[1].y);
        agg[1].x = fmaf(z1.z, wc.x, agg[1].x); agg[1].y = fmaf(z1.z, wc.y, agg[1].y);
        agg[1].x = fmaf(z1.w, wd.x, agg[1].x); agg[1].y = fmaf(z1.w, wd.y, agg[1].y);
        agg[2].x = fmaf(z2.x, wa.x, agg[2].x); agg[2].y = fmaf(z2.x, wa.y, agg[2].y);
        agg[2].x = fmaf(z2.y, wb.x, agg[2].x); agg[2].y = fmaf(z2.y, wb.y, agg[2].y);
        agg[2].x = fmaf(z2.z, wc.x, agg[2].x); agg[2].y = fmaf(z2.z, wc.y, agg[2].y);
        agg[2].x = fmaf(z2.w, wd.x, agg[2].x); agg[2].y = fmaf(z2.w, wd.y, agg[2].y);
        agg[3].x = fmaf(z3.x, wa.x, agg[3].x); agg[3].y = fmaf(z3.x, wa.y, agg[3].y);
        agg[3].x = fmaf(z3.y, wb.x, agg[3].x); agg[3].y = fmaf(z3.y, wb.y, agg[3].y);
        agg[3].x = fmaf(z3.z, wc.x, agg[3].x); agg[3].y = fmaf(z3.z, wc.y, agg[3].y);
        agg[3].x = fmaf(z3.w, wd.x, agg[3].x); agg[3].y = fmaf(z3.w, wd.y, agg[3].y);
    }

    float2 ls = make_float2(0.f, 0.f), lq = make_float2(0.f, 0.f);
    #pragma unroll
    for (int i = 0; i < 4; i++) {
        float2 p = make_float2(sCB[2 * lane], sCB[2 * lane + 1]);
        const float* xr = x + (size_t)nn[i] * 8;
        #pragma unroll
        for (int f = 0; f < 8; f++) {
            float xv = __ldg(xr + f);
            float2 rw = sRoot[f][lane];
            p.x = fmaf(xv, rw.x, p.x);
            p.y = fmaf(xv, rw.y, p.y);
        }
        float invd = sInvDeg[nlocbase + i];
        p.x = fmaf(agg[i].x, invd, p.x);
        p.y = fmaf(agg[i].y, invd, p.y);
        if (valid[i]) {
            g_pre[(size_t)nn[i] * 64 + 2 * lane]     = p.x;
            g_pre[(size_t)nn[i] * 64 + 2 * lane + 1] = p.y;
            ls.x += p.x; ls.y += p.y;
            lq.x = fmaf(p.x, p.x, lq.x);
            lq.y = fmaf(p.y, p.y, lq.y);
        }
    }
    redS[warp][lane] = ls;
    redQ[warp][lane] = lq;
    __syncthreads();
    if (tid < 32) {
        float2 S = make_float2(0.f, 0.f), Q = make_float2(0.f, 0.f);
        #pragma unroll
        for (int w = 0; w < 8; w++) {
            S.x += redS[w][tid].x; S.y += redS[w][tid].y;
            Q.x += redQ[w][tid].x; Q.y += redQ[w][tid].y;
        }
        atomicAdd(&g_colsum[2 * tid],     S.x);
        atomicAdd(&g_colsum[2 * tid + 1], S.y);
        atomicAdd(&g_colsq[2 * tid],      Q.x);
        atomicAdd(&g_colsq[2 * tid + 1],  Q.y);
    }
}

// ---------------- BN + relu + per-graph pool (one block per graph, no atomics) ----------------
__global__ void k_pool(const float* __restrict__ gam,
                       const float* __restrict__ bet,
                       int N) {
    __shared__ float sScale[64], sShift[64];
    __shared__ float redS[8][64];
    __shared__ float redM[8][64];

    int tid = threadIdx.x;
    if (tid < 64) {
        float invN = 1.f / (float)N;
        float m = g_colsum[tid] * invN;
        float v = g_colsq[tid] * invN - m * m;
        float r = rsqrtf(v + EPS);
        float sc = r * __ldg(&gam[tid]);
        sScale[tid] = sc;
        sShift[tid] = __ldg(&bet[tid]) - m * sc;
    }
    __syncthreads();

    int rg = tid >> 6;       // 0..7 row groups
    int c  = tid & 63;
    int g = blockIdx.x;
    int s0 = g_start[g], s1 = g_start[g + 1];
    float sc = sScale[c], sh = sShift[c];

    float sum = 0.f, mx = 0.f;
    for (int n = s0 + rg; n < s1; n += 8) {
        float p = __ldg(&g_pre[(size_t)n * 64 + c]);
        float h = fmaxf(fmaf(p, sc, sh), 0.f);
        sum += h;
        mx = fmaxf(mx, h);
    }
    redS[rg][c] = sum;
    redM[rg][c] = mx;
    __syncthreads();
    if (tid < 64) {
        float S = 0.f, M = 0.f;
        #pragma unroll
        for (int r = 0; r < 8; r++) { S += redS[r][tid]; M = fmaxf(M, redM[r][tid]); }
        int cnt = s1 - s0;
        g_gfeat[g * 128 + tid]      = S / fmaxf((float)cnt, 1.f);
        g_gfeat[g * 128 + 64 + tid] = (cnt > 0) ? M : 0.f;
    }
}

// ---------------- fused linear + BN(over 64 rows) + relu; block owns 32 output cols ----------------
__global__ void k_layer(const float* __restrict__ in,   // [64, I]
                        const float* __restrict__ w,    // [I, O]
                        const float* __restrict__ b,
                        const float* __restrict__ gam,
                        const float* __restrict__ bet,
                        float* __restrict__ out,        // [64, O]
                        int I, int O) {
    extern __shared__ float sIn[];                       // 64*I floats
    __shared__ float redS[8][32], redQ[8][32];
    __shared__ float sScale[32], sShift[32];

    int tid = threadIdx.x;
    for (int idx = tid; idx < 64 * I; idx += blockDim.x) sIn[idx] = in[idx];
    __syncthreads();

    int c = tid & 31, r0 = tid >> 5;
    int cg = blockIdx.x * 32 + c;

    float acc[8];
    float bv = __ldg(&b[cg]);
    #pragma unroll
    for (int i = 0; i < 8; i++) acc[i] = bv;

    for (int k = 0; k < I; k++) {
        float wv = __ldg(&w[k * O + cg]);
        #pragma unroll
        for (int i = 0; i < 8; i++)
            acc[i] = fmaf(sIn[(r0 + 8 * i) * I + k], wv, acc[i]);
    }

    float s = 0.f, q = 0.f;
    #pragma unroll
    for (int i = 0; i < 8; i++) { s += acc[i]; q = fmaf(acc[i], acc[i], q); }
    redS[r0][c] = s;
    redQ[r0][c] = q;
    __syncthreads();
    if (tid < 32) {
        float S = 0.f, Q = 0.f;
        #pragma unroll
        for (int w8 = 0; w8 < 8; w8++) { S += redS[w8][tid]; Q += redQ[w8][tid]; }
        float m = S * (1.f / 64.f);
        float v = Q * (1.f / 64.f) - m * m;
        float r = rsqrtf(v + EPS);
        float sc = r * __ldg(&gam[blockIdx.x * 32 + tid]);
        sScale[tid] = sc;
        sShift[tid] = __ldg(&bet[blockIdx.x * 32 + tid]) - m * sc;
    }
    __syncthreads();
    float sc = sScale[c], sh = sShift[c];
    #pragma unroll
    for (int i = 0; i < 8; i++)
        out[(r0 + 8 * i) * O + cg] = fmaxf(fmaf(acc[i], sc, sh), 0.f);
}

// ---------------- final projection [64,64]@[64,10] ----------------
__global__ void k_out(const float* __restrict__ wout,
                      const float* __restrict__ bout,
                      float* __restrict__ out) {
    int t = threadIdx.x;
    if (t >= 640) return;
    int g = t / 10, o = t % 10;
    float s = __ldg(&bout[o]);
    #pragma unroll
    for (int k = 0; k < 64; k++)
        s = fmaf(g_y3[g * 64 + k], __ldg(&wout[k * 10 + o]), s);
    out[t] = s;
}

// ---------------- launch ----------------
extern "C" void kernel_launch(void* const* d_in, const int* in_sizes, int n_in,
                              void* d_out, int out_size) {
    const float* x      = (const float*)d_in[0];
    const int*   ei     = (const int*)  d_in[1];
    const float* ea     = (const float*)d_in[2];
    const int*   batch  = (const int*)  d_in[3];
    const float* w_e1   = (const float*)d_in[4];
    const float* b_e1   = (const float*)d_in[5];
    const float* w_e2   = (const float*)d_in[6];
    const float* b_e2   = (const float*)d_in[7];
    const float* root   = (const float*)d_in[8];
    const float* cbias  = (const float*)d_in[9];
    const float* g_bnc  = (const float*)d_in[10];
    const float* b_bnc  = (const float*)d_in[11];
    const float* w1     = (const float*)d_in[12];
    const float* b1     = (const float*)d_in[13];
    const float* g1     = (const float*)d_in[14];
    const float* be1    = (const float*)d_in[15];
    const float* w2     = (const float*)d_in[16];
    const float* b2     = (const float*)d_in[17];
    const float* g2     = (const float*)d_in[18];
    const float* be2    = (const float*)d_in[19];
    const float* w3     = (const float*)d_in[20];
    const float* b3     = (const float*)d_in[21];
    const float* g3     = (const float*)d_in[22];
    const float* be3    = (const float*)d_in[23];
    const float* wout   = (const float*)d_in[24];
    const float* bout   = (const float*)d_in[25];

    int N = in_sizes[0] / 8;
    int E = in_sizes[2] / 8;
    if (N > NMAX) N = NMAX;
    if (E > EMAX) E = EMAX;

    void *p_gfeat, *p_y1, *p_y2, *p_y3;
    cudaGetSymbolAddress(&p_gfeat, g_gfeat);
    cudaGetSymbolAddress(&p_y1, g_y1);
    cudaGetSymbolAddress(&p_y2, g_y2);
    cudaGetSymbolAddress(&p_y3, g_y3);

    const int fusedSmem = ZDIM * 32 * 8 + 32 * ZDIM * 4;   // sWc + sZ = 52224 B
    cudaFuncSetAttribute(k_fused, cudaFuncAttributeMaxDynamicSharedMemorySize, fusedSmem);
    cudaFuncSetAttribute(k_layer, cudaFuncAttributeMaxDynamicSharedMemorySize,
                         64 * 256 * (int)sizeof(float));

    k_zero<<<128, 256>>>(N);
    k_hist<<<(E + 255) / 256, 256>>>(ei, E);
    k_scan<<<1, 1024>>>(N, E);
    k_starts<<<1, 64>>>(batch, N);
    k_scatter<<<(E + 255) / 256, 256>>>(ei, ea, E);
    k_fused<<<(N + 31) / 32, 256, fusedSmem>>>(x, w_e1, b_e1, w_e2, b_e2, root, cbias, N);
    k_pool<<<GRAPHS, 512>>>(g_bnc, b_bnc, N);
    k_layer<<<8, 256, 64 * 128 * sizeof(float)>>>((const float*)p_gfeat, w1, b1, g1, be1, (float*)p_y1, 128, 256);
    k_layer<<<4, 256, 64 * 256 * sizeof(float)>>>((const float*)p_y1,    w2, b2, g2, be2, (float*)p_y2, 256, 128);
    k_layer<<<2, 256, 64 * 128 * sizeof(float)>>>((const float*)p_y2,    w3, b3, g3, be3, (float*)p_y3, 128, 64);
    k_out<<<1, 640>>>(wout, bout, (float*)d_out);
}

// round 3
// speedup vs baseline: 1.3896x; 1.3896x over previous
#include <cuda_runtime.h>
#include <cstdint>

#define NMAX   50000
#define EMAX   500000
#define ZDIM   136      // 16 (he) x 8 (x) + 8 (x bias lanes)
#define GRAPHS 64
#define EPS    1e-5f
#define SCAN_B 128
#define SCAN_T 512
#define CHUNK  512      // staged edges per block iteration

// ---------------- scratch (device globals; no allocation allowed) ----------------
__device__ int      g_cnt[NMAX];                    // degree histogram
__device__ int      g_off[NMAX + 1];                // CSR offsets
__device__ int      g_cur[NMAX];                    // scatter cursors
__device__ int      g_bsum[SCAN_B];                 // scan block sums
__device__ int      g_bbase[SCAN_B];                // scan block bases
__device__ int2     g_epay[EMAX];                   // dst-sorted (edge_id, src)
__device__ float    g_pre[(size_t)NMAX * 64];       // NNConv pre-BN output
__device__ float    g_colsum[64];
__device__ float    g_colsq[64];
__device__ int      g_start[GRAPHS + 1];            // graph boundaries
__device__ float    g_gfeat[GRAPHS * 128];
__device__ float    g_y1[GRAPHS * 256];
__device__ float    g_y2[GRAPHS * 128];
__device__ float    g_y3[GRAPHS * 64];

// ---------------- zero + graph boundary scatter ----------------
__global__ void k_zero(const int* __restrict__ batch, int N) {
    int i = blockIdx.x * blockDim.x + threadIdx.x;
    int stride = gridDim.x * blockDim.x;
    for (int n = i; n < N; n += stride) {
        g_cnt[n] = 0;
        int bn = __ldg(&batch[n]);
        int bp = (n == 0) ? -1 : __ldg(&batch[n - 1]);
        for (int g = bp + 1; g <= bn; g++) g_start[g] = n;
        if (n == N - 1) {
            for (int g = bn + 1; g <= GRAPHS; g++) g_start[g] = N;
        }
    }
    if (i < 64) { g_colsum[i] = 0.f; g_colsq[i] = 0.f; }
}

// ---------------- histogram of dst ----------------
__global__ void k_hist(const int* __restrict__ ei, int E) {
    int e = blockIdx.x * blockDim.x + threadIdx.x;
    if (e < E) atomicAdd(&g_cnt[__ldg(&ei[E + e])], 1);
}

// ---------------- multi-block scan: A (local prefix), B (block bases), C (add) ----------------
__global__ void k_scanA(int N) {
    __shared__ int sv[SCAN_T];
    int tid = threadIdx.x, b = blockIdx.x;
    int C = (N + gridDim.x - 1) / gridDim.x;
    int base = b * C, end = min(base + C, N);
    int run = 0;
    for (int t0 = base; t0 < end; t0 += SCAN_T) {
        int idx = t0 + tid;
        int v = (idx < end) ? g_cnt[idx] : 0;
        sv[tid] = v;
        __syncthreads();
        for (int off = 1; off < SCAN_T; off <<= 1) {
            int u = (tid >= off) ? sv[tid - off] : 0;
            __syncthreads();
            sv[tid] += u;
            __syncthreads();
        }
        if (idx < end) g_off[idx] = run + sv[tid] - v;   // local exclusive
        run += sv[SCAN_T - 1];
        __syncthreads();
    }
    if (tid == 0) g_bsum[b] = run;
}

__global__ void k_scanB() {
    __shared__ int sv[SCAN_B];
    int tid = threadIdx.x;
    int v = g_bsum[tid];
    sv[tid] = v;
    __syncthreads();
    for (int off = 1; off < SCAN_B; off <<= 1) {
        int u = (tid >= off) ? sv[tid - off] : 0;
        __syncthreads();
        sv[tid] += u;
        __syncthreads();
    }
    g_bbase[tid] = sv[tid] - v;   // exclusive
}

__global__ void k_scanC(int N, int E) {
    int tid = threadIdx.x, b = blockIdx.x;
    int C = (N + gridDim.x - 1) / gridDim.x;
    int base = b * C, end = min(base + C, N);
    int add = g_bbase[b];
    for (int idx = base + tid; idx < end; idx += SCAN_T) {
        int o = g_off[idx] + add;
        g_off[idx] = o;
        g_cur[idx] = o;
    }
    if (b == gridDim.x - 1 && tid == 0) g_off[N] = E;
}

// ---------------- scatter (edge_id, src) into dst-sorted order ----------------
__global__ void k_scatter(const int* __restrict__ ei, int E) {
    int e = blockIdx.x * blockDim.x + threadIdx.x;
    if (e >= E) return;
    int dst = __ldg(&ei[E + e]);
    int src = __ldg(&ei[e]);
    int pos = atomicAdd(&g_cur[dst], 1);
    g_epay[pos] = make_int2(e, src);
}

// ---------------- fused: stage edges -> z accumulate -> node GEMM -> BN stats ----------------
// block = 256 threads, 32 nodes per block.
__global__ void k_fused(const float* __restrict__ x,
                        const float* __restrict__ ea,
                        const float* __restrict__ w_e1,
                        const float* __restrict__ b_e1,
                        const float* __restrict__ w_e2,
                        const float* __restrict__ b_e2,
                        const float* __restrict__ root,
                        const float* __restrict__ cbias,
                        int N) {
    extern __shared__ char dynsmem[];
    float2* sWc = (float2*)dynsmem;                                 // [136][32] f2 = 34816 B
    float*  sZ  = (float*)(dynsmem + ZDIM * 32 * 8);                // [32][136]   = 17408 B
    float*  sHe = (float*)(dynsmem + ZDIM * 32 * 8 + 32 * ZDIM * 4);        // [CHUNK][16] = 32768 B
    float*  sX  = sHe + CHUNK * 16;                                 // [CHUNK][8]  = 16384 B

    __shared__ float  sW1[128];
    __shared__ float  sB1[16];
    __shared__ float2 sRoot[8][32];
    __shared__ float  sCB[64];
    __shared__ float  sInvDeg[32];
    __shared__ float2 redS[8][32];
    __shared__ float2 redQ[8][32];

    int tid = threadIdx.x;

    // ---- load weights ----
    if (tid < 128) sW1[tid] = w_e1[tid];
    if (tid < 16)  sB1[tid] = b_e1[tid];
    for (int idx = tid; idx < ZDIM * 32; idx += blockDim.x) {
        int k = idx >> 5, l = idx & 31;
        int h0 = 2 * l;
        float a, b;
        if (k < 128) {
            int j = k >> 3, f = k & 7;
            a = w_e2[j * 512 + f * 64 + h0];
            b = w_e2[j * 512 + f * 64 + h0 + 1];
        } else {
            int f = k - 128;
            a = b_e2[f * 64 + h0];
            b = b_e2[f * 64 + h0 + 1];
        }
        sWc[k * 32 + l] = make_float2(a, b);
    }
    for (int idx = tid; idx < 8 * 32; idx += blockDim.x) {
        int f = idx >> 5, l = idx & 31;
        sRoot[f][l] = make_float2(root[f * 64 + 2 * l], root[f * 64 + 2 * l + 1]);
    }
    if (tid < 64) sCB[tid] = cbias[tid];

    // block edge range
    int nFirst = blockIdx.x * 32;
    int nLast  = min(nFirst + 32, N);
    int eBeg = __ldg(&g_off[nFirst]);
    int eEnd = __ldg(&g_off[nLast]);

    // per-thread node assignment for phase 1
    int gnode = tid >> 3;          // 0..31
    int sub   = tid & 7;           // owns he[2*sub], he[2*sub+1]
    int n = nFirst + gnode;
    int j0 = 2 * sub;
    int o0 = 0, o1 = 0;
    if (n < N) {
        o0 = __ldg(&g_off[n]);
        o1 = __ldg(&g_off[n + 1]);
    }

    float zacc[16];
    #pragma unroll
    for (int i = 0; i < 16; i++) zacc[i] = 0.f;
    float xs[8];
    #pragma unroll
    for (int i = 0; i < 8; i++) xs[i] = 0.f;

    __syncthreads();

    // ---- chunked staging + accumulation ----
    for (int c0 = eBeg; c0 < eEnd; c0 += CHUNK) {
        int nE = min(CHUNK, eEnd - c0);

        // stage: gather + edge MLP
        for (int i = tid; i < nE; i += 256) {
            int2 es = __ldg(&g_epay[c0 + i]);
            float4 a0 = __ldg((const float4*)(ea + (size_t)es.x * 8));
            float4 a1 = __ldg((const float4*)(ea + (size_t)es.x * 8 + 4));
            float4 x0 = __ldg((const float4*)(x + (size_t)es.y * 8));
            float4 x1 = __ldg((const float4*)(x + (size_t)es.y * 8 + 4));

            float he[16];
            #pragma unroll
            for (int j = 0; j < 16; j++) {
                float s = sB1[j];
                s = fmaf(a0.x, sW1[0 * 16 + j], s);
                s = fmaf(a0.y, sW1[1 * 16 + j], s);
                s = fmaf(a0.z, sW1[2 * 16 + j], s);
                s = fmaf(a0.w, sW1[3 * 16 + j], s);
                s = fmaf(a1.x, sW1[4 * 16 + j], s);
                s = fmaf(a1.y, sW1[5 * 16 + j], s);
                s = fmaf(a1.z, sW1[6 * 16 + j], s);
                s = fmaf(a1.w, sW1[7 * 16 + j], s);
                he[j] = fmaxf(s, 0.f);
            }
            float4* hrow = (float4*)(sHe + i * 16);
            hrow[0] = make_float4(he[0], he[1], he[2], he[3]);
            hrow[1] = make_float4(he[4], he[5], he[6], he[7]);
            hrow[2] = make_float4(he[8], he[9], he[10], he[11]);
            hrow[3] = make_float4(he[12], he[13], he[14], he[15]);
            float4* xrow = (float4*)(sX + i * 8);
            xrow[0] = x0;
            xrow[1] = x1;
        }
        __syncthreads();

        // accumulate this node's edges within chunk
        int c1 = c0 + nE;
        int lo = max(o0, c0), hi = min(o1, c1);
        for (int i = lo; i < hi; i++) {
            int li = i - c0;
            float h0 = sHe[li * 16 + j0];
            float h1 = sHe[li * 16 + j0 + 1];
            float4 x0 = *(const float4*)(sX + li * 8);
            float4 x1 = *(const float4*)(sX + li * 8 + 4);
            zacc[0] = fmaf(h0, x0.x, zacc[0]);
            zacc[1] = fmaf(h0, x0.y, zacc[1]);
            zacc[2] = fmaf(h0, x0.z, zacc[2]);
            zacc[3] = fmaf(h0, x0.w, zacc[3]);
            zacc[4] = fmaf(h0, x1.x, zacc[4]);
            zacc[5] = fmaf(h0, x1.y, zacc[5]);
            zacc[6] = fmaf(h0, x1.z, zacc[6]);
            zacc[7] = fmaf(h0, x1.w, zacc[7]);
            zacc[8]  = fmaf(h1, x0.x, zacc[8]);
            zacc[9]  = fmaf(h1, x0.y, zacc[9]);
            zacc[10] = fmaf(h1, x0.z, zacc[10]);
            zacc[11] = fmaf(h1, x0.w, zacc[11]);
            zacc[12] = fmaf(h1, x1.x, zacc[12]);
            zacc[13] = fmaf(h1, x1.y, zacc[13]);
            zacc[14] = fmaf(h1, x1.z, zacc[14]);
            zacc[15] = fmaf(h1, x1.w, zacc[15]);
            if (sub == 0) {
                xs[0] += x0.x; xs[1] += x0.y; xs[2] += x0.z; xs[3] += x0.w;
                xs[4] += x1.x; xs[5] += x1.y; xs[6] += x1.z; xs[7] += x1.w;
            }
        }
        __syncthreads();
    }

    // dump z to shared
    {
        float* zrow = sZ + gnode * ZDIM;
        #pragma unroll
        for (int f = 0; f < 8; f++) {
            zrow[j0 * 8 + f]       = zacc[f];
            zrow[(j0 + 1) * 8 + f] = zacc[8 + f];
        }
        if (sub == 0) {
            #pragma unroll
            for (int f = 0; f < 8; f++) zrow[128 + f] = xs[f];
            sInvDeg[gnode] = 1.f / fmaxf((float)(o1 - o0), 1.f);
        }
    }
    __syncthreads();

    // ---- phase 2: pre = (z @ Wc)*invdeg + x@root + bias; BN partial stats ----
    int warp = tid >> 5, lane = tid & 31;
    int nlocbase = warp * 4;
    int nbase = nFirst + nlocbase;

    int  nn[4];
    bool valid[4];
    #pragma unroll
    for (int i = 0; i < 4; i++) {
        int nd = nbase + i;
        valid[i] = (nd < N);
        nn[i] = valid[i] ? nd : 0;
    }

    const float4* zr0 = (const float4*)(sZ + (nlocbase + 0) * ZDIM);
    const float4* zr1 = (const float4*)(sZ + (nlocbase + 1) * ZDIM);
    const float4* zr2 = (const float4*)(sZ + (nlocbase + 2) * ZDIM);
    const float4* zr3 = (const float4*)(sZ + (nlocbase + 3) * ZDIM);

    float2 agg[4];
    #pragma unroll
    for (int i = 0; i < 4; i++) agg[i] = make_float2(0.f, 0.f);

    #pragma unroll 2
    for (int kk = 0; kk < ZDIM / 4; kk++) {
        float4 z0 = zr0[kk];
        float4 z1 = zr1[kk];
        float4 z2 = zr2[kk];
        float4 z3 = zr3[kk];
        float2 wa = sWc[(4 * kk + 0) * 32 + lane];
        float2 wb = sWc[(4 * kk + 1) * 32 + lane];
        float2 wc = sWc[(4 * kk + 2) * 32 + lane];
        float2 wd = sWc[(4 * kk + 3) * 32 + lane];
        agg[0].x = fmaf(z0.x, wa.x, agg[0].x); agg[0].y = fmaf(z0.x, wa.y, agg[0].y);
        agg[0].x = fmaf(z0.y, wb.x, agg[0].x); agg[0].y = fmaf(z0.y, wb.y, agg[0].y);
        agg[0].x = fmaf(z0.z, wc.x, agg[0].x); agg[0].y = fmaf(z0.z, wc.y, agg[0].y);
        agg[0].x = fmaf(z0.w, wd.x, agg[0].x); agg[0].y = fmaf(z0.w, wd.y, agg[0].y);
        agg[1].x = fmaf(z1.x, wa.x, agg[1].x); agg[1].y = fmaf(z1.x, wa.y, agg[1].y);
        agg[1].x = fmaf(z1.y, wb.x, agg[1].x); agg[1].y = fmaf(z1.y, wb.y, agg[1].y);
        agg[1].x = fmaf(z1.z, wc.x, agg[1].x); agg[1].y = fmaf(z1.z, wc.y, agg[1].y);
        agg[1].x = fmaf(z1.w, wd.x, agg[1].x); agg[1].y = fmaf(z1.w, wd.y, agg[1].y);
        agg[2].x = fmaf(z2.x, wa.x, agg[2].x); agg[2].y = fmaf(z2.x, wa.y, agg[2].y);
        agg[2].x = fmaf(z2.y, wb.x, agg[2].x); agg[2].y = fmaf(z2.y, wb.y, agg[2].y);
        agg[2].x = fmaf(z2.z, wc.x, agg[2].x); agg[2].y = fmaf(z2.z, wc.y, agg[2].y);
        agg[2].x = fmaf(z2.w, wd.x, agg[2].x); agg[2].y = fmaf(z2.w, wd.y, agg[2].y);
        agg[3].x = fmaf(z3.x, wa.x, agg[3].x); agg[3].y = fmaf(z3.x, wa.y, agg[3].y);
        agg[3].x = fmaf(z3.y, wb.x, agg[3].x); agg[3].y = fmaf(z3.y, wb.y, agg[3].y);
        agg[3].x = fmaf(z3.z, wc.x, agg[3].x); agg[3].y = fmaf(z3.z, wc.y, agg[3].y);
        agg[3].x = fmaf(z3.w, wd.x, agg[3].x); agg[3].y = fmaf(z3.w, wd.y, agg[3].y);
    }

    float2 ls = make_float2(0.f, 0.f), lq = make_float2(0.f, 0.f);
    #pragma unroll
    for (int i = 0; i < 4; i++) {
        float2 p = make_float2(sCB[2 * lane], sCB[2 * lane + 1]);
        const float* xr = x + (size_t)nn[i] * 8;
        #pragma unroll
        for (int f = 0; f < 8; f++) {
            float xv = __ldg(xr + f);
            float2 rw = sRoot[f][lane];
            p.x = fmaf(xv, rw.x, p.x);
            p.y = fmaf(xv, rw.y, p.y);
        }
        float invd = sInvDeg[nlocbase + i];
        p.x = fmaf(agg[i].x, invd, p.x);
        p.y = fmaf(agg[i].y, invd, p.y);
        if (valid[i]) {
            g_pre[(size_t)nn[i] * 64 + 2 * lane]     = p.x;
            g_pre[(size_t)nn[i] * 64 + 2 * lane + 1] = p.y;
            ls.x += p.x; ls.y += p.y;
            lq.x = fmaf(p.x, p.x, lq.x);
            lq.y = fmaf(p.y, p.y, lq.y);
        }
    }
    redS[warp][lane] = ls;
    redQ[warp][lane] = lq;
    __syncthreads();
    if (tid < 32) {
        float2 S = make_float2(0.f, 0.f), Q = make_float2(0.f, 0.f);
        #pragma unroll
        for (int w = 0; w < 8; w++) {
            S.x += redS[w][tid].x; S.y += redS[w][tid].y;
            Q.x += redQ[w][tid].x; Q.y += redQ[w][tid].y;
        }
        atomicAdd(&g_colsum[2 * tid],     S.x);
        atomicAdd(&g_colsum[2 * tid + 1], S.y);
        atomicAdd(&g_colsq[2 * tid],      Q.x);
        atomicAdd(&g_colsq[2 * tid + 1],  Q.y);
    }
}

// ---------------- BN + relu + per-graph pool (one block per graph) ----------------
__global__ void k_pool(const float* __restrict__ gam,
                       const float* __restrict__ bet,
                       int N) {
    __shared__ float sScale[64], sShift[64];
    __shared__ float redS[8][64];
    __shared__ float redM[8][64];

    int tid = threadIdx.x;
    if (tid < 64) {
        float invN = 1.f / (float)N;
        float m = g_colsum[tid] * invN;
        float v = g_colsq[tid] * invN - m * m;
        float r = rsqrtf(v + EPS);
        float sc = r * __ldg(&gam[tid]);
        sScale[tid] = sc;
        sShift[tid] = __ldg(&bet[tid]) - m * sc;
    }
    __syncthreads();

    int rg = tid >> 6;
    int c  = tid & 63;
    int g = blockIdx.x;
    int s0 = g_start[g], s1 = g_start[g + 1];
    float sc = sScale[c], sh = sShift[c];

    float sum = 0.f, mx = 0.f;
    for (int n = s0 + rg; n < s1; n += 8) {
        float p = __ldg(&g_pre[(size_t)n * 64 + c]);
        float h = fmaxf(fmaf(p, sc, sh), 0.f);
        sum += h;
        mx = fmaxf(mx, h);
    }
    redS[rg][c] = sum;
    redM[rg][c] = mx;
    __syncthreads();
    if (tid < 64) {
        float S = 0.f, M = 0.f;
        #pragma unroll
        for (int r = 0; r < 8; r++) { S += redS[r][tid]; M = fmaxf(M, redM[r][tid]); }
        int cnt = s1 - s0;
        g_gfeat[g * 128 + tid]      = S / fmaxf((float)cnt, 1.f);
        g_gfeat[g * 128 + 64 + tid] = (cnt > 0) ? M : 0.f;
    }
}

// ---------------- fused linear + BN(over 64 rows) + relu ----------------
__global__ void k_layer(const float* __restrict__ in,   // [64, I]
                        const float* __restrict__ w,    // [I, O]
                        const float* __restrict__ b,
                        const float* __restrict__ gam,
                        const float* __restrict__ bet,
                        float* __restrict__ out,        // [64, O]
                        int I, int O) {
    extern __shared__ float sIn[];
    __shared__ float redS[8][32], redQ[8][32];
    __shared__ float sScale[32], sShift[32];

    int tid = threadIdx.x;
    for (int idx = tid; idx < 64 * I; idx += blockDim.x) sIn[idx] = in[idx];
    __syncthreads();

    int c = tid & 31, r0 = tid >> 5;
    int cg = blockIdx.x * 32 + c;

    float acc[8];
    float bv = __ldg(&b[cg]);
    #pragma unroll
    for (int i = 0; i < 8; i++) acc[i] = bv;

    for (int k = 0; k < I; k++) {
        float wv = __ldg(&w[k * O + cg]);
        #pragma unroll
        for (int i = 0; i < 8; i++)
            acc[i] = fmaf(sIn[(r0 + 8 * i) * I + k], wv, acc[i]);
    }

    float s = 0.f, q = 0.f;
    #pragma unroll
    for (int i = 0; i < 8; i++) { s += acc[i]; q = fmaf(acc[i], acc[i], q); }
    redS[r0][c] = s;
    redQ[r0][c] = q;
    __syncthreads();
    if (tid < 32) {
        float S = 0.f, Q = 0.f;
        #pragma unroll
        for (int w8 = 0; w8 < 8; w8++) { S += redS[w8][tid]; Q += redQ[w8][tid]; }
        float m = S * (1.f / 64.f);
        float v = Q * (1.f / 64.f) - m * m;
        float r = rsqrtf(v + EPS);
        float sc = r * __ldg(&gam[blockIdx.x * 32 + tid]);
        sScale[tid] = sc;
        sShift[tid] = __ldg(&bet[blockIdx.x * 32 + tid]) - m * sc;
    }
    __syncthreads();
    float sc = sScale[c], sh = sShift[c];
    #pragma unroll
    for (int i = 0; i < 8; i++)
        out[(r0 + 8 * i) * O + cg] = fmaxf(fmaf(acc[i], sc, sh), 0.f);
}

// ---------------- final projection [64,64]@[64,10] ----------------
__global__ void k_out(const float* __restrict__ wout,
                      const float* __restrict__ bout,
                      float* __restrict__ out) {
    int t = threadIdx.x;
    if (t >= 640) return;
    int g = t / 10, o = t % 10;
    float s = __ldg(&bout[o]);
    #pragma unroll
    for (int k = 0; k < 64; k++)
        s = fmaf(g_y3[g * 64 + k], __ldg(&wout[k * 10 + o]), s);
    out[t] = s;
}

// ---------------- launch ----------------
extern "C" void kernel_launch(void* const* d_in, const int* in_sizes, int n_in,
                              void* d_out, int out_size) {
    const float* x      = (const float*)d_in[0];
    const int*   ei     = (const int*)  d_in[1];
    const float* ea     = (const float*)d_in[2];
    const int*   batch  = (const int*)  d_in[3];
    const float* w_e1   = (const float*)d_in[4];
    const float* b_e1   = (const float*)d_in[5];
    const float* w_e2   = (const float*)d_in[6];
    const float* b_e2   = (const float*)d_in[7];
    const float* root   = (const float*)d_in[8];
    const float* cbias  = (const float*)d_in[9];
    const float* g_bnc  = (const float*)d_in[10];
    const float* b_bnc  = (const float*)d_in[11];
    const float* w1     = (const float*)d_in[12];
    const float* b1     = (const float*)d_in[13];
    const float* g1     = (const float*)d_in[14];
    const float* be1    = (const float*)d_in[15];
    const float* w2     = (const float*)d_in[16];
    const float* b2     = (const float*)d_in[17];
    const float* g2     = (const float*)d_in[18];
    const float* be2    = (const float*)d_in[19];
    const float* w3     = (const float*)d_in[20];
    const float* b3     = (const float*)d_in[21];
    const float* g3     = (const float*)d_in[22];
    const float* be3    = (const float*)d_in[23];
    const float* wout   = (const float*)d_in[24];
    const float* bout   = (const float*)d_in[25];

    int N = in_sizes[0] / 8;
    int E = in_sizes[2] / 8;
    if (N > NMAX) N = NMAX;
    if (E > EMAX) E = EMAX;

    void *p_gfeat, *p_y1, *p_y2, *p_y3;
    cudaGetSymbolAddress(&p_gfeat, g_gfeat);
    cudaGetSymbolAddress(&p_y1, g_y1);
    cudaGetSymbolAddress(&p_y2, g_y2);
    cudaGetSymbolAddress(&p_y3, g_y3);

    const int fusedSmem = ZDIM * 32 * 8            // sWc
                        + 32 * ZDIM * 4            // sZ
                        + CHUNK * 16 * 4           // sHe
                        + CHUNK * 8 * 4;           // sX  = 101376 B
    cudaFuncSetAttribute(k_fused, cudaFuncAttributeMaxDynamicSharedMemorySize, fusedSmem);
    cudaFuncSetAttribute(k_layer, cudaFuncAttributeMaxDynamicSharedMemorySize,
                         64 * 256 * (int)sizeof(float));

    k_zero<<<128, 256>>>(batch, N);
    k_hist<<<(E + 255) / 256, 256>>>(ei, E);
    k_scanA<<<SCAN_B, SCAN_T>>>(N);
    k_scanB<<<1, SCAN_B>>>();
    k_scanC<<<SCAN_B, SCAN_T>>>(N, E);
    k_scatter<<<(E + 255) / 256, 256>>>(ei, E);
    k_fused<<<(N + 31) / 32, 256, fusedSmem>>>(x, ea, w_e1, b_e1, w_e2, b_e2, root, cbias, N);
    k_pool<<<GRAPHS, 512>>>(g_bnc, b_bnc, N);
    k_layer<<<8, 256, 64 * 128 * sizeof(float)>>>((const float*)p_gfeat, w1, b1, g1, be1, (float*)p_y1, 128, 256);
    k_layer<<<4, 256, 64 * 256 * sizeof(float)>>>((const float*)p_y1,    w2, b2, g2, be2, (float*)p_y2, 256, 128);
    k_layer<<<2, 256, 64 * 128 * sizeof(float)>>>((const float*)p_y2,    w3, b3, g3, be3, (float*)p_y3, 128, 64);
    k_out<<<1, 640>>>(wout, bout, (float*)d_out);
}